// round 11
// baseline (speedup 1.0000x reference)
#include <cuda_runtime.h>

#define G        64
#define IMGSZ    512
#define CHSTRIDE (IMGSZ * IMGSZ)
#define NTHREADS 512

#define EDGE_SCALE (1.0f / 0.875f)   // all patch-edge wsums are 7/8

// S=4 tmp: [3][8][272] floats; patch col j at row offset j+6; phase-2 chunk i
// reads float4 indices i+1, i+2 (row = 68 float4s). Pads {4,5,262,263} = 0.
#define RP4 272
#define CH4 (8 * RP4)    // 2176
// S=2 tmp: [3][16][136]; col j at offset j+5; chunk i reads float2 idx i+2,i+3
// (row = 68 float2s). Pads {4,133} = 0.
#define RP2 136
#define CH2 (16 * RP2)   // 2176

__device__ __forceinline__ float4 ldg4(const float* p) {
    return __ldg((const float4*)p);
}

// ======================= S = 4 (img4 -> window 2) =======================
// Vertical-first; weights [1,3,5,7,7,5,3,1]/32. Chunk m = rows [4m-2,4m+2):
// s=[1,3,5,7]/32, t=[7,5,3,1]/32, out_y = s_y + t_{y+1}. Rows outside
// patch/image read as 0; outputs y/i == 0/63 scaled by EDGE_SCALE.
// Phase 1: lane = 4-column group anchored at A=bx&~3 (LDG.128), masked
// scalar STS into shifted smem row. 65 groups x 3 ch x 2 h = 390 items.
__device__ void ds4_slice3(const float* __restrict__ imgb, float* __restrict__ ob,
                           int by, int bx, int y0, float* __restrict__ tmp) {
    const int tid = threadIdx.x;

    // zero pads: 24 rows (3ch x 8) x offsets {4,5,262,263}
    if (tid < 96) {
        int rs = tid >> 2, k = tid & 3;
        tmp[rs * RP4 + ((k < 2) ? 4 + k : 260 + k)] = 0.f;
    }

    const int A = bx & ~3;           // rounds toward -inf
    const int d = bx - A;            // 0..3
    int cg, slot;
    if (tid < 384) { cg = tid & 63; slot = tid >> 6; }
    else           { cg = 64;       slot = tid - 384; }

    if (slot < 6) {
        const int ch  = slot >> 1;
        const int h   = slot & 1;
        const int ylo = y0 + 4 * h;
        const int rlo = 4 * ylo - 2;
        const int cb  = A + 4 * cg;            // aligned image col base
        const int jb  = 4 * cg - d;            // patch col of lane's k=0
        const float* cimg = imgb + (size_t)ch * CHSTRIDE;
        float* trow = tmp + ch * CH4 + (4 * h) * RP4 + 6 + jb;

        if (cb >= 0 && cb + 3 < IMGSZ) {
            float4 sp = make_float4(0.f, 0.f, 0.f, 0.f);
#pragma unroll
            for (int cm = 0; cm <= 4; cm++) {
                float4 v[4];
#pragma unroll
                for (int k = 0; k < 4; k++) {
                    int r  = rlo + 4 * cm + k;
                    int gy = by + r;
                    bool ok = ((unsigned)r < 256u) & ((unsigned)gy < (unsigned)IMGSZ);
                    v[k] = ok ? ldg4(cimg + (size_t)gy * IMGSZ + cb)
                              : make_float4(0.f, 0.f, 0.f, 0.f);
                }
                float4 s, t;
                s.x = fmaf(7.f/32, v[3].x, fmaf(5.f/32, v[2].x, fmaf(3.f/32, v[1].x, (1.f/32)*v[0].x)));
                s.y = fmaf(7.f/32, v[3].y, fmaf(5.f/32, v[2].y, fmaf(3.f/32, v[1].y, (1.f/32)*v[0].y)));
                s.z = fmaf(7.f/32, v[3].z, fmaf(5.f/32, v[2].z, fmaf(3.f/32, v[1].z, (1.f/32)*v[0].z)));
                s.w = fmaf(7.f/32, v[3].w, fmaf(5.f/32, v[2].w, fmaf(3.f/32, v[1].w, (1.f/32)*v[0].w)));
                t.x = fmaf(1.f/32, v[3].x, fmaf(3.f/32, v[2].x, fmaf(5.f/32, v[1].x, (7.f/32)*v[0].x)));
                t.y = fmaf(1.f/32, v[3].y, fmaf(3.f/32, v[2].y, fmaf(5.f/32, v[1].y, (7.f/32)*v[0].y)));
                t.z = fmaf(1.f/32, v[3].z, fmaf(3.f/32, v[2].z, fmaf(5.f/32, v[1].z, (7.f/32)*v[0].z)));
                t.w = fmaf(1.f/32, v[3].w, fmaf(3.f/32, v[2].w, fmaf(5.f/32, v[1].w, (7.f/32)*v[0].w)));
                if (cm > 0) {
                    int y = ylo + cm - 1;
                    float es = (y == 0 || y == 63) ? EDGE_SCALE : 1.0f;
                    float* dst = trow + (cm - 1) * RP4;
                    if ((unsigned)(jb + 0) < 256u) dst[0] = (sp.x + t.x) * es;
                    if ((unsigned)(jb + 1) < 256u) dst[1] = (sp.y + t.y) * es;
                    if ((unsigned)(jb + 2) < 256u) dst[2] = (sp.z + t.z) * es;
                    if ((unsigned)(jb + 3) < 256u) dst[3] = (sp.w + t.w) * es;
                }
                sp = s;
            }
        } else {
            // column-boundary fallback: per valid patch col, scalar chain or zeros
#pragma unroll
            for (int k = 0; k < 4; k++) {
                int j = jb + k;
                if ((unsigned)j >= 256u) continue;
                int c = cb + k;
                if ((unsigned)c >= (unsigned)IMGSZ) {
#pragma unroll
                    for (int cm = 1; cm <= 4; cm++) trow[(cm - 1) * RP4 + k] = 0.f;
                    continue;
                }
                float sp = 0.f;
#pragma unroll
                for (int cm = 0; cm <= 4; cm++) {
                    float v[4];
#pragma unroll
                    for (int kk = 0; kk < 4; kk++) {
                        int r  = rlo + 4 * cm + kk;
                        int gy = by + r;
                        bool ok = ((unsigned)r < 256u) & ((unsigned)gy < (unsigned)IMGSZ);
                        v[kk] = ok ? __ldg(cimg + (size_t)gy * IMGSZ + c) : 0.f;
                    }
                    float s = fmaf(7.f/32, v[3], fmaf(5.f/32, v[2], fmaf(3.f/32, v[1], (1.f/32)*v[0])));
                    float t = fmaf(1.f/32, v[3], fmaf(3.f/32, v[2], fmaf(5.f/32, v[1], (7.f/32)*v[0])));
                    if (cm > 0) {
                        int y = ylo + cm - 1;
                        float es = (y == 0 || y == 63) ? EDGE_SCALE : 1.0f;
                        trow[(cm - 1) * RP4 + k] = (sp + t) * es;
                    }
                    sp = s;
                }
            }
        }
    }
    __syncthreads();

    // ---- phase 2: horizontal, aligned float4 chunks, 3 ch per thread ----
    const float4* t4 = (const float4*)tmp;   // ch stride 544, row stride 68
    {
        int yy = tid >> 6, i = tid & 63;      // 8*64 == NTHREADS
        float* op = ob + (y0 + yy) * G + i;
        float es = (i == 0 || i == 63) ? EDGE_SCALE : 1.0f;
#pragma unroll
        for (int ch = 0; ch < 3; ch++) {
            float4 a = t4[ch * 544 + yy * 68 + i + 1];
            float4 b = t4[ch * 544 + yy * 68 + i + 2];
            float acc = (1.f/32)*a.x + (3.f/32)*a.y + (5.f/32)*a.z + (7.f/32)*a.w
                      + (7.f/32)*b.x + (5.f/32)*b.y + (3.f/32)*b.z + (1.f/32)*b.w;
            op[ch * (G * G)] = acc * es;
        }
    }
}

// ======================= S = 2 (img2 -> window 1) =======================
// Weights [1,3,3,1]/8; chunk m = rows {2m-1,2m}: s=[1,3]/8, t=[3,1]/8.
// 16 output rows per block. 33 groups x 3 ch x 4 h = 396 items.
__device__ void ds2_slice3(const float* __restrict__ imgb, float* __restrict__ ob,
                           int by, int bx, int y0, float* __restrict__ tmp) {
    const int tid = threadIdx.x;

    // zero pads: 48 rows x offsets {4,133}
    if (tid < 96) {
        int rs = tid >> 1, k = tid & 1;
        tmp[rs * RP2 + (k ? 133 : 4)] = 0.f;
    }

    const int A = bx & ~3;
    const int d = bx - A;
    int cg, slot;
    if (tid < 384) { cg = tid & 31; slot = tid >> 5; }
    else           { cg = 32;       slot = tid - 384; }

    if (slot < 12) {
        const int ch  = slot >> 2;
        const int h   = slot & 3;
        const int ylo = y0 + 4 * h;
        const int rlo = 2 * ylo - 1;
        const int cb  = A + 4 * cg;
        const int jb  = 4 * cg - d;
        const float* cimg = imgb + (size_t)ch * CHSTRIDE;
        float* trow = tmp + ch * CH2 + (4 * h) * RP2 + 5 + jb;

        if (cb >= 0 && cb + 3 < IMGSZ) {
            float4 sp = make_float4(0.f, 0.f, 0.f, 0.f);
#pragma unroll
            for (int cm = 0; cm <= 4; cm++) {
                float4 v0, v1;
                {
                    int r  = rlo + 2 * cm;
                    int gy = by + r;
                    bool ok = ((unsigned)r < 128u) & ((unsigned)gy < (unsigned)IMGSZ);
                    v0 = ok ? ldg4(cimg + (size_t)gy * IMGSZ + cb)
                            : make_float4(0.f, 0.f, 0.f, 0.f);
                }
                {
                    int r  = rlo + 2 * cm + 1;
                    int gy = by + r;
                    bool ok = ((unsigned)r < 128u) & ((unsigned)gy < (unsigned)IMGSZ);
                    v1 = ok ? ldg4(cimg + (size_t)gy * IMGSZ + cb)
                            : make_float4(0.f, 0.f, 0.f, 0.f);
                }
                float4 s, t;
                s.x = fmaf(3.f/8, v1.x, (1.f/8)*v0.x);
                s.y = fmaf(3.f/8, v1.y, (1.f/8)*v0.y);
                s.z = fmaf(3.f/8, v1.z, (1.f/8)*v0.z);
                s.w = fmaf(3.f/8, v1.w, (1.f/8)*v0.w);
                t.x = fmaf(1.f/8, v1.x, (3.f/8)*v0.x);
                t.y = fmaf(1.f/8, v1.y, (3.f/8)*v0.y);
                t.z = fmaf(1.f/8, v1.z, (3.f/8)*v0.z);
                t.w = fmaf(1.f/8, v1.w, (3.f/8)*v0.w);
                if (cm > 0) {
                    int y = ylo + cm - 1;
                    float es = (y == 0 || y == 63) ? EDGE_SCALE : 1.0f;
                    float* dst = trow + (cm - 1) * RP2;
                    if ((unsigned)(jb + 0) < 128u) dst[0] = (sp.x + t.x) * es;
                    if ((unsigned)(jb + 1) < 128u) dst[1] = (sp.y + t.y) * es;
                    if ((unsigned)(jb + 2) < 128u) dst[2] = (sp.z + t.z) * es;
                    if ((unsigned)(jb + 3) < 128u) dst[3] = (sp.w + t.w) * es;
                }
                sp = s;
            }
        } else {
#pragma unroll
            for (int k = 0; k < 4; k++) {
                int j = jb + k;
                if ((unsigned)j >= 128u) continue;
                int c = cb + k;
                if ((unsigned)c >= (unsigned)IMGSZ) {
#pragma unroll
                    for (int cm = 1; cm <= 4; cm++) trow[(cm - 1) * RP2 + k] = 0.f;
                    continue;
                }
                float sp = 0.f;
#pragma unroll
                for (int cm = 0; cm <= 4; cm++) {
                    float v[2];
#pragma unroll
                    for (int kk = 0; kk < 2; kk++) {
                        int r  = rlo + 2 * cm + kk;
                        int gy = by + r;
                        bool ok = ((unsigned)r < 128u) & ((unsigned)gy < (unsigned)IMGSZ);
                        v[kk] = ok ? __ldg(cimg + (size_t)gy * IMGSZ + c) : 0.f;
                    }
                    float s = fmaf(3.f/8, v[1], (1.f/8)*v[0]);
                    float t = fmaf(1.f/8, v[1], (3.f/8)*v[0]);
                    if (cm > 0) {
                        int y = ylo + cm - 1;
                        float es = (y == 0 || y == 63) ? EDGE_SCALE : 1.0f;
                        trow[(cm - 1) * RP2 + k] = (sp + t) * es;
                    }
                    sp = s;
                }
            }
        }
    }
    __syncthreads();

    // ---- phase 2: horizontal, aligned float2 chunks, 3 ch per thread ----
    const float2* t2 = (const float2*)tmp;   // ch stride 1088, row stride 68
#pragma unroll
    for (int u = 0; u < 2; u++) {
        int idx = tid + u * NTHREADS;        // 16*64 = 1024
        int yy = idx >> 6, i = idx & 63;
        float* op = ob + (y0 + yy) * G + i;
        float es = (i == 0 || i == 63) ? EDGE_SCALE : 1.0f;
#pragma unroll
        for (int ch = 0; ch < 3; ch++) {
            float2 a = t2[ch * 1088 + yy * 68 + i + 2];
            float2 b = t2[ch * 1088 + yy * 68 + i + 3];
            float acc = (1.f/8)*a.x + (3.f/8)*a.y + (3.f/8)*b.x + (1.f/8)*b.y;
            op[ch * (G * G)] = acc * es;
        }
    }
}

// Grid (832 blocks), heavy work first:
//   [0, 512)   : S=4, 8 slices x 8 rows per b (3 channels fused)
//   [512, 768) : S=2, 4 slices x 16 rows per b
//   [768, 832) : direct 64x64 zero-padded crop of img0, 3 channels
__global__ __launch_bounds__(NTHREADS, 3)
void glimpse_kernel(const float* __restrict__ img0,
                    const float* __restrict__ img2,
                    const float* __restrict__ img4,
                    const float* __restrict__ loc,
                    float* __restrict__ out) {
    extern __shared__ __align__(16) float tmp[];

    int blk = blockIdx.x;
    int sel, b, slice;
    if (blk < 512)      { sel = 0; b = blk >> 3;         slice = blk & 7; }
    else if (blk < 768) { sel = 1; b = (blk - 512) >> 2; slice = (blk - 512) & 3; }
    else                { sel = 2; b = blk - 768;        slice = 0; }

    // start index, matching jnp: trunc(0.5f * ((loc + 1.0f) * 511.0f))
    float lx = loc[2 * b + 0];
    float ly = loc[2 * b + 1];
    int sx = (int)(0.5f * ((lx + 1.0f) * 511.0f));
    int sy = (int)(0.5f * ((ly + 1.0f) * 511.0f));

    if (sel == 0) {
        const float* imgb = img4 + (size_t)b * 3 * CHSTRIDE;
        float* ob = out + (size_t)(b * 9 + 6) * (G * G);
        ds4_slice3(imgb, ob, sy - 128, sx - 128, slice * 8, tmp);
    } else if (sel == 1) {
        const float* imgb = img2 + (size_t)b * 3 * CHSTRIDE;
        float* ob = out + (size_t)(b * 9 + 3) * (G * G);
        ds2_slice3(imgb, ob, sy - 64, sx - 64, slice * 16, tmp);
    } else {
        const float* imgb = img0 + (size_t)b * 3 * CHSTRIDE;
        float* ob = out + (size_t)(b * 9 + 0) * (G * G);
        int by = sy - G / 2, bx = sx - G / 2;
#pragma unroll
        for (int u = 0; u < 8; u++) {
            int idx = threadIdx.x + u * NTHREADS;   // 4096 positions
            int y = idx >> 6, x = idx & 63;
            int gy = by + y, gx = bx + x;
            bool ok = (unsigned)gy < IMGSZ && (unsigned)gx < IMGSZ;
            const float* q = imgb + (size_t)(ok ? gy : 0) * IMGSZ + (ok ? gx : 0);
#pragma unroll
            for (int ch = 0; ch < 3; ch++)
                ob[ch * (G * G) + y * G + x] = ok ? __ldg(q + ch * CHSTRIDE) : 0.f;
        }
    }
}

extern "C" void kernel_launch(void* const* d_in, const int* in_sizes, int n_in,
                              void* d_out, int out_size) {
    const float* img0 = (const float*)d_in[0];
    const float* img2 = (const float*)d_in[1];
    const float* img4 = (const float*)d_in[2];
    const float* loc  = (const float*)d_in[3];
    float* out = (float*)d_out;

    const size_t smem = 3 * CH4 * sizeof(float);   // 26112 B (== 3*CH2*4)
    cudaFuncSetAttribute(glimpse_kernel,
                         cudaFuncAttributeMaxDynamicSharedMemorySize, (int)smem);
    glimpse_kernel<<<832, NTHREADS, smem>>>(img0, img2, img4, loc, out);
}